// round 1
// baseline (speedup 1.0000x reference)
#include <cuda_runtime.h>
#include <cstdint>

// ---------------------------------------------------------------------------
// Problem:
//   c1..c4 scores from an FPN head.
//   Heavy part: three 3x3 SAME convs (128->128) + ReLU, then linear epilogue
//   (1x1 tidy conv to 1 channel, column pooling over full height).
//   Everything after ReLU is linear -> fuse into per-block epilogue.
//
// Inputs (metadata order):
//  0 p2 [64,128,64,128]  1 p3 [64,128,32,64]  2 p4 [64,128,16,32]
//  3 p5 [64,512,8,16]
//  4 w_s1[128,128,3,3] 5 b_s1[128] 6 w_s2 7 b_s2 8 w_s3 9 b_s3
// 10 w_t1[128] 11 b_t1[1] 12 w_t2 13 b_t2 14 w_t3 15 b_t3 16 w_t4[512] 17 b_t4
// 18 w_pl1[64] 19 b_pl1 20 w_pl2[32] 21 b_pl2 22 w_pl3[16] 23 b_pl3
// 24 w_pl4[8] 25 b_pl4
// Output: [64, 240] fp32  (c1:128 | c2:64 | c3:32 | c4:16)
// ---------------------------------------------------------------------------

#define KWEL 147456  // 128*128*9 per level
__device__ float g_wT[3 * KWEL];  // weights transposed to [c][tap][o]

// ---- f32x2 packed helpers (sm_103a; ptxas won't auto-fuse, use PTX) -------
__device__ __forceinline__ unsigned long long dup2(float x) {
    unsigned long long r;
    asm("mov.b64 %0, {%1, %1};" : "=l"(r) : "f"(x));
    return r;
}
__device__ __forceinline__ void fma2(unsigned long long& a,
                                     unsigned long long w,
                                     unsigned long long x) {
    asm("fma.rn.f32x2 %0, %1, %2, %0;" : "+l"(a) : "l"(w), "l"(x));
}
__device__ __forceinline__ float2 unpk(unsigned long long v) {
    float2 r;
    asm("mov.b64 {%0, %1}, %2;" : "=f"(r.x), "=f"(r.y) : "l"(v));
    return r;
}

// ---- weight transpose: w[o][c][tap] -> g_wT[level][(c*9+tap)*128 + o] ------
__global__ void transpose_w_kernel(const float* __restrict__ w1,
                                   const float* __restrict__ w2,
                                   const float* __restrict__ w3) {
    int i = blockIdx.x * blockDim.x + threadIdx.x;
    if (i >= 3 * KWEL) return;
    int l = i / KWEL;
    int r = i - l * KWEL;           // r = o*1152 + c*9 + tap (coalesced read)
    int o = r / 1152;
    int rem = r - o * 1152;         // c*9 + tap
    const float* src = (l == 0) ? w1 : (l == 1) ? w2 : w3;
    g_wT[l * KWEL + rem * 128 + o] = src[r];
}

// ---- fused conv3x3 + ReLU + tidy(1x1) + column pooling --------------------
// Block: one (batch, TW-wide column stripe), full height H, all 128 outs.
// 256 threads: og = tid&7 (16 out-channels each), pg = tid>>3 (4 positions).
template <int H, int W, int TW, int NH, int NW, int BASE>
__global__ void __launch_bounds__(256)
conv_level_kernel(const float* __restrict__ x,   // [64,128,H,W]
                  const float* __restrict__ wT,  // g_wT slice for this level
                  const float* __restrict__ bs,  // [128]
                  const float* __restrict__ wt,  // [128]
                  const float* __restrict__ bt,  // [1]
                  const float* __restrict__ wpl, // [H]
                  const float* __restrict__ bpl, // [1]
                  float* __restrict__ out) {
    constexpr int CC = 8;
    constexpr int HP = H + 2;
    constexpr int WP = TW + 2;

    const int tid = threadIdx.x;
    const int WT_ = W / TW;
    const int b   = blockIdx.x / WT_;
    const int w0  = (blockIdx.x - b * WT_) * TW;
    const int og  = tid & 7;
    const int pg  = tid >> 3;
    const int h0  = (pg * 4) / TW;
    const int w0l = (pg * 4) % TW;

    __shared__ float sIn[CC * HP * WP];
    __shared__ float sW[CC * 9 * 128];
    __shared__ float sWt[128];
    __shared__ float sBs[128];
    __shared__ float sPl[H];
    __shared__ float sCol[TW];

    if (tid < 128) { sWt[tid] = wt[tid]; sBs[tid] = bs[tid]; }
    if (tid < H)  sPl[tid] = wpl[tid];
    if (tid < TW) sCol[tid] = 0.f;

    unsigned long long acc[4][8];
#pragma unroll
    for (int p = 0; p < 4; p++)
#pragma unroll
        for (int k = 0; k < 8; k++) acc[p][k] = 0ull;

    const float* xb = x + (size_t)b * 128 * H * W;

    for (int c0 = 0; c0 < 128; c0 += CC) {
        __syncthreads();
        // stage input chunk (with halo, zero-padded)
        constexpr int EI = CC * HP * WP;
        for (int i = tid; i < EI; i += 256) {
            int cc = i / (HP * WP);
            int rr = i - cc * (HP * WP);
            int hh = rr / WP;
            int ww = rr - hh * WP;
            int gh = hh - 1;
            int gw = w0 + ww - 1;
            float v = 0.f;
            if (gh >= 0 && gh < H && gw >= 0 && gw < W)
                v = xb[((c0 + cc) * H + gh) * W + gw];
            sIn[i] = v;
        }
        // stage weights (contiguous in transposed layout)
        {
            const float4* src = (const float4*)(wT + c0 * 1152);
            float4* dst = (float4*)sW;
            for (int i = tid; i < CC * 1152 / 4; i += 256) dst[i] = src[i];
        }
        __syncthreads();

#pragma unroll
        for (int cc = 0; cc < CC; cc++) {
            // register-cache duplicated inputs for this thread's positions
            unsigned long long rd[NH + 2][NW + 2];
#pragma unroll
            for (int i = 0; i < NH + 2; i++)
#pragma unroll
                for (int j = 0; j < NW + 2; j++)
                    rd[i][j] = dup2(sIn[(cc * HP + h0 + i) * WP + w0l + j]);

#pragma unroll
            for (int dy = 0; dy < 3; dy++)
#pragma unroll
                for (int dx = 0; dx < 3; dx++) {
                    const int tap = dy * 3 + dx;
                    const ulonglong2* wp = (const ulonglong2*)
                        &sW[(cc * 9 + tap) * 128 + og * 16];
                    unsigned long long wv[8];
#pragma unroll
                    for (int q = 0; q < 4; q++) {
                        ulonglong2 v = wp[q];
                        wv[2 * q]     = v.x;
                        wv[2 * q + 1] = v.y;
                    }
#pragma unroll
                    for (int ih = 0; ih < NH; ih++)
#pragma unroll
                        for (int jw = 0; jw < NW; jw++) {
                            const int pi = ih * NW + jw;
                            const unsigned long long xd = rd[ih + dy][jw + dx];
#pragma unroll
                            for (int k = 0; k < 8; k++) fma2(acc[pi][k], wv[k], xd);
                        }
                }
        }
    }

    // ---- epilogue: bias + ReLU + dot(w_t) + height pooling ----------------
    float ps[4];
#pragma unroll
    for (int pi = 0; pi < 4; pi++) {
        float sp = 0.f;
#pragma unroll
        for (int k = 0; k < 8; k++) {
            float2 v = unpk(acc[pi][k]);
            int o = og * 16 + 2 * k;
            float z0 = fmaxf(v.x + sBs[o], 0.f);
            float z1 = fmaxf(v.y + sBs[o + 1], 0.f);
            sp = fmaf(z0, sWt[o], sp);
            sp = fmaf(z1, sWt[o + 1], sp);
        }
        ps[pi] = sp;
    }
    // reduce over the 8 og-lanes (aligned 8-lane groups within each warp)
#pragma unroll
    for (int pi = 0; pi < 4; pi++) {
        ps[pi] += __shfl_xor_sync(0xffffffffu, ps[pi], 1);
        ps[pi] += __shfl_xor_sync(0xffffffffu, ps[pi], 2);
        ps[pi] += __shfl_xor_sync(0xffffffffu, ps[pi], 4);
    }
    if (og == 0) {
        const float btv = bt[0];
#pragma unroll
        for (int pi = 0; pi < 4; pi++) {
            int ih = pi / NW, jw = pi - ih * NW;
            int h = h0 + ih, wl = w0l + jw;
            atomicAdd(&sCol[wl], sPl[h] * (ps[pi] + btv));
        }
    }
    __syncthreads();
    if (tid < TW) out[b * 240 + BASE + w0 + tid] = sCol[tid] + bpl[0];
}

// ---- p5 path: tidy 1x1 (512->1) + pool over h=8, memory bound -------------
__global__ void p5_kernel(const float* __restrict__ p5,
                          const float* __restrict__ wt,   // [512]
                          const float* __restrict__ bt,   // [1]
                          const float* __restrict__ wpl,  // [8]
                          const float* __restrict__ bpl,  // [1]
                          float* __restrict__ out) {
    const int b = blockIdx.x;
    const int tid = threadIdx.x;
    const int w = tid & 15;
    const int g = tid >> 4;  // 16 channel groups
    __shared__ float red[256];
    __shared__ float spl[8];
    if (tid < 8) spl[tid] = wpl[tid];
    __syncthreads();

    const float* pb = p5 + (size_t)b * 512 * 8 * 16;
    float accv = 0.f;
    for (int c = g; c < 512; c += 16) {
        float wc = wt[c];
        const float* row = pb + (size_t)c * 8 * 16 + w;
#pragma unroll
        for (int h = 0; h < 8; h++)
            accv = fmaf(wc * spl[h], row[h * 16], accv);
    }
    red[tid] = accv;
    __syncthreads();
    if (tid < 16) {
        float s = 0.f;
#pragma unroll
        for (int gg = 0; gg < 16; gg++) s += red[gg * 16 + tid];
        float sumpl = 0.f;
#pragma unroll
        for (int h = 0; h < 8; h++) s = s;  // keep order simple
        for (int h = 0; h < 8; h++) sumpl += spl[h];
        out[b * 240 + 224 + tid] = s + bt[0] * sumpl + bpl[0];
    }
}

// ---------------------------------------------------------------------------
extern "C" void kernel_launch(void* const* d_in, const int* in_sizes, int n_in,
                              void* d_out, int out_size) {
    const float* p2   = (const float*)d_in[0];
    const float* p3   = (const float*)d_in[1];
    const float* p4   = (const float*)d_in[2];
    const float* p5   = (const float*)d_in[3];
    const float* w_s1 = (const float*)d_in[4];
    const float* b_s1 = (const float*)d_in[5];
    const float* w_s2 = (const float*)d_in[6];
    const float* b_s2 = (const float*)d_in[7];
    const float* w_s3 = (const float*)d_in[8];
    const float* b_s3 = (const float*)d_in[9];
    const float* w_t1 = (const float*)d_in[10];
    const float* b_t1 = (const float*)d_in[11];
    const float* w_t2 = (const float*)d_in[12];
    const float* b_t2 = (const float*)d_in[13];
    const float* w_t3 = (const float*)d_in[14];
    const float* b_t3 = (const float*)d_in[15];
    const float* w_t4 = (const float*)d_in[16];
    const float* b_t4 = (const float*)d_in[17];
    const float* w_pl1 = (const float*)d_in[18];
    const float* b_pl1 = (const float*)d_in[19];
    const float* w_pl2 = (const float*)d_in[20];
    const float* b_pl2 = (const float*)d_in[21];
    const float* w_pl3 = (const float*)d_in[22];
    const float* b_pl3 = (const float*)d_in[23];
    const float* w_pl4 = (const float*)d_in[24];
    const float* b_pl4 = (const float*)d_in[25];
    float* out = (float*)d_out;

    // transpose conv weights into g_wT
    {
        int n = 3 * KWEL;
        transpose_w_kernel<<<(n + 255) / 256, 256>>>(w_s1, w_s2, w_s3);
    }

    float* wT;
    cudaGetSymbolAddress((void**)&wT, g_wT);

    // L1: H=64 W=128 TW=2  (NH=2, NW=2), out base 0
    conv_level_kernel<64, 128, 2, 2, 2, 0><<<64 * 64, 256>>>(
        p2, wT + 0 * KWEL, b_s1, w_t1, b_t1, w_pl1, b_pl1, out);
    // L2: H=32 W=64 TW=4  (NH=1, NW=4), base 128
    conv_level_kernel<32, 64, 4, 1, 4, 128><<<64 * 16, 256>>>(
        p3, wT + 1 * KWEL, b_s2, w_t2, b_t2, w_pl2, b_pl2, out);
    // L3: H=16 W=32 TW=8  (NH=1, NW=4), base 192
    conv_level_kernel<16, 32, 8, 1, 4, 192><<<64 * 4, 256>>>(
        p4, wT + 2 * KWEL, b_s3, w_t3, b_t3, w_pl3, b_pl3, out);
    // p5 path, base 224
    p5_kernel<<<64, 256>>>(p5, w_t4, b_t4, w_pl4, b_pl4, out);
}

// round 2
// speedup vs baseline: 2.9018x; 2.9018x over previous
#include <cuda_runtime.h>
#include <cstdint>

// ---------------------------------------------------------------------------
// FPN head: three 3x3 SAME convs (128->128) + ReLU, fused with the linear
// epilogue (1x1 tidy conv -> 1 channel, column pooling over height).
//
// R1 redesign: out-channel group is WARP-uniform so weight LDS.128 is a full
// broadcast (1 wavefront, was 4). Lane = spatial position (8x16 tile, 4
// positions/lane). Channel reduction via shared atomics; height pooling via
// one global atomicAdd per column (out pre-initialized with bpl by init_out).
//
// Output: [64, 240] fp32  (c1:128 | c2:64 | c3:32 | c4:16)
// ---------------------------------------------------------------------------

#define KWEL 147456  // 128*128*9 per level
__device__ float g_wT[3 * KWEL];  // weights transposed to [c][tap][o]

typedef unsigned long long ull;

// ---- f32x2 packed helpers (sm_103a; only reachable via inline PTX) --------
__device__ __forceinline__ ull dup2(float x) {
    ull r;
    asm("mov.b64 %0, {%1, %1};" : "=l"(r) : "f"(x));
    return r;
}
__device__ __forceinline__ void fma2(ull& a, ull w, ull x) {
    asm("fma.rn.f32x2 %0, %1, %2, %0;" : "+l"(a) : "l"(w), "l"(x));
}
__device__ __forceinline__ float2 unpk(ull v) {
    float2 r;
    asm("mov.b64 {%0, %1}, %2;" : "=f"(r.x), "=f"(r.y) : "l"(v));
    return r;
}

// ---- weight transpose: w[o][c][tap] -> g_wT[level][(c*9+tap)*128 + o] -----
__global__ void transpose_w_kernel(const float* __restrict__ w1,
                                   const float* __restrict__ w2,
                                   const float* __restrict__ w3) {
    int i = blockIdx.x * blockDim.x + threadIdx.x;
    if (i >= 3 * KWEL) return;
    int l = i / KWEL;
    int r = i - l * KWEL;           // r = o*1152 + c*9 + tap (coalesced read)
    int o = r / 1152;
    int rem = r - o * 1152;         // c*9 + tap
    const float* src = (l == 0) ? w1 : (l == 1) ? w2 : w3;
    g_wT[l * KWEL + rem * 128 + o] = src[r];
}

// ---- out initialization: write bpl for c1/c2/c3 regions (atomics add rest)
__global__ void init_out_kernel(const float* __restrict__ bpl1,
                                const float* __restrict__ bpl2,
                                const float* __restrict__ bpl3,
                                float* __restrict__ out) {
    int i = blockIdx.x * blockDim.x + threadIdx.x;
    if (i >= 64 * 224) return;
    int j = i % 224;
    float v = (j < 128) ? bpl1[0] : (j < 192) ? bpl2[0] : bpl3[0];
    int b = i / 224;
    out[b * 240 + j] = v;
}

// ---- fused conv3x3 + ReLU + tidy(1x1) + column pooling --------------------
// Block: 256 threads = 8 warps. warp = out-channel group (16 ch each, weight
// loads broadcast). Lane: lh = lane>>2 (8 rows), lw4 = (lane&3)*4 (4 cols of
// 4 positions). Tile = 8 rows x 16 cols.
template <int H, int W, int BASE>
__global__ void __launch_bounds__(256, 2)
conv_level_kernel(const float* __restrict__ x,   // [64,128,H,W]
                  const float* __restrict__ wT,  // g_wT slice for this level
                  const float* __restrict__ bs,  // [128]
                  const float* __restrict__ wt,  // [128]
                  const float* __restrict__ bt,  // [1]
                  const float* __restrict__ wpl, // [H]
                  float* __restrict__ out) {
    constexpr int CC = 8;
    constexpr int NBW = W / 16;
    constexpr int NBH = H / 8;

    const int tid  = threadIdx.x;
    const int warp = tid >> 5;
    const int lane = tid & 31;
    const int lh   = lane >> 2;
    const int lw4  = (lane & 3) * 4;

    const int bid = blockIdx.x;
    const int b   = bid / (NBH * NBW);
    const int rr_ = bid - b * (NBH * NBW);
    const int h0g = (rr_ / NBW) * 8;
    const int w0g = (rr_ % NBW) * 16;

    __shared__ float sIn[CC * 10 * 21];   // 21-float row pitch: conflict-free
    __shared__ float sW[CC * 9 * 128];
    __shared__ float sWt[128];
    __shared__ float sBs[128];
    __shared__ float sPl8[8];
    __shared__ float sTile[128];

    if (tid < 128) { sWt[tid] = wt[tid]; sBs[tid] = bs[tid]; sTile[tid] = 0.f; }
    if (tid < 8) sPl8[tid] = wpl[h0g + tid];

    ull acc[4][8];
#pragma unroll
    for (int p = 0; p < 4; p++)
#pragma unroll
        for (int k = 0; k < 8; k++) acc[p][k] = 0ull;

    const float* xb = x + (size_t)b * 128 * H * W;

    for (int c0 = 0; c0 < 128; c0 += CC) {
        __syncthreads();
        // stage input tile (10 x 18 window per channel, pitch 21)
        for (int i = tid; i < CC * 10 * 18; i += 256) {
            int cc = i / 180;
            int r2 = i - cc * 180;
            int hh = r2 / 18;
            int ww = r2 - hh * 18;
            int gh = h0g + hh - 1;
            int gw = w0g + ww - 1;
            float v = 0.f;
            if (gh >= 0 && gh < H && gw >= 0 && gw < W)
                v = xb[((c0 + cc) * H + gh) * W + gw];
            sIn[(cc * 10 + hh) * 21 + ww] = v;
        }
        // stage weights (contiguous in transposed layout)
        {
            const float4* src = (const float4*)(wT + c0 * 1152);
            float4* dst = (float4*)sW;
            for (int i = tid; i < CC * 1152 / 4; i += 256) dst[i] = src[i];
        }
        __syncthreads();

#pragma unroll
        for (int cc = 0; cc < CC; cc++) {
#pragma unroll
            for (int dy = 0; dy < 3; dy++) {
                ull rd6[6];
#pragma unroll
                for (int j = 0; j < 6; j++)
                    rd6[j] = dup2(sIn[(cc * 10 + lh + dy) * 21 + lw4 + j]);
#pragma unroll
                for (int dx = 0; dx < 3; dx++) {
                    // broadcast weight load: address uniform within warp
                    const ulonglong2* wp = (const ulonglong2*)
                        &sW[((cc * 9 + dy * 3 + dx) << 7) + (warp << 4)];
                    ull wv[8];
#pragma unroll
                    for (int q = 0; q < 4; q++) {
                        ulonglong2 v = wp[q];
                        wv[2 * q]     = v.x;
                        wv[2 * q + 1] = v.y;
                    }
#pragma unroll
                    for (int p = 0; p < 4; p++) {
                        const ull xd = rd6[p + dx];
#pragma unroll
                        for (int k = 0; k < 8; k++) fma2(acc[p][k], wv[k], xd);
                    }
                }
            }
        }
    }

    // ---- epilogue: bias + ReLU + dot(w_t), reduce channels across warps ---
#pragma unroll
    for (int p = 0; p < 4; p++) {
        float sp = 0.f;
#pragma unroll
        for (int k = 0; k < 8; k++) {
            float2 v = unpk(acc[p][k]);
            int o = warp * 16 + 2 * k;
            sp = fmaf(fmaxf(v.x + sBs[o], 0.f), sWt[o], sp);
            sp = fmaf(fmaxf(v.y + sBs[o + 1], 0.f), sWt[o + 1], sp);
        }
        atomicAdd(&sTile[lh * 16 + lw4 + p], sp);
    }
    __syncthreads();

    // height pooling for this tile; one global atomic per column
    if (tid < 16) {
        const float btv = bt[0];
        float s = 0.f;
#pragma unroll
        for (int h = 0; h < 8; h++)
            s = fmaf(sPl8[h], sTile[h * 16 + tid] + btv, s);
        atomicAdd(&out[b * 240 + BASE + w0g + tid], s);
    }
}

// ---- p5 path: tidy 1x1 (512->1) + pool over h=8, memory bound -------------
__global__ void p5_kernel(const float* __restrict__ p5,
                          const float* __restrict__ wt,   // [512]
                          const float* __restrict__ bt,   // [1]
                          const float* __restrict__ wpl,  // [8]
                          const float* __restrict__ bpl,  // [1]
                          float* __restrict__ out) {
    const int b = blockIdx.x;
    const int tid = threadIdx.x;
    const int w = tid & 15;
    const int g = tid >> 4;  // 16 channel groups
    __shared__ float red[256];
    __shared__ float spl[8];
    if (tid < 8) spl[tid] = wpl[tid];
    __syncthreads();

    const float* pb = p5 + (size_t)b * 512 * 8 * 16;
    float accv = 0.f;
    for (int c = g; c < 512; c += 16) {
        float wc = wt[c];
        const float* row = pb + (size_t)c * 8 * 16 + w;
#pragma unroll
        for (int h = 0; h < 8; h++)
            accv = fmaf(wc * spl[h], row[h * 16], accv);
    }
    red[tid] = accv;
    __syncthreads();
    if (tid < 16) {
        float s = 0.f;
#pragma unroll
        for (int gg = 0; gg < 16; gg++) s += red[gg * 16 + tid];
        float sumpl = 0.f;
#pragma unroll
        for (int h = 0; h < 8; h++) sumpl += spl[h];
        out[b * 240 + 224 + tid] = s + bt[0] * sumpl + bpl[0];
    }
}

// ---------------------------------------------------------------------------
extern "C" void kernel_launch(void* const* d_in, const int* in_sizes, int n_in,
                              void* d_out, int out_size) {
    const float* p2   = (const float*)d_in[0];
    const float* p3   = (const float*)d_in[1];
    const float* p4   = (const float*)d_in[2];
    const float* p5   = (const float*)d_in[3];
    const float* w_s1 = (const float*)d_in[4];
    const float* b_s1 = (const float*)d_in[5];
    const float* w_s2 = (const float*)d_in[6];
    const float* b_s2 = (const float*)d_in[7];
    const float* w_s3 = (const float*)d_in[8];
    const float* b_s3 = (const float*)d_in[9];
    const float* w_t1 = (const float*)d_in[10];
    const float* b_t1 = (const float*)d_in[11];
    const float* w_t2 = (const float*)d_in[12];
    const float* b_t2 = (const float*)d_in[13];
    const float* w_t3 = (const float*)d_in[14];
    const float* b_t3 = (const float*)d_in[15];
    const float* w_t4 = (const float*)d_in[16];
    const float* b_t4 = (const float*)d_in[17];
    const float* w_pl1 = (const float*)d_in[18];
    const float* b_pl1 = (const float*)d_in[19];
    const float* w_pl2 = (const float*)d_in[20];
    const float* b_pl2 = (const float*)d_in[21];
    const float* w_pl3 = (const float*)d_in[22];
    const float* b_pl3 = (const float*)d_in[23];
    const float* w_pl4 = (const float*)d_in[24];
    const float* b_pl4 = (const float*)d_in[25];
    float* out = (float*)d_out;

    // transpose conv weights into g_wT
    {
        int n = 3 * KWEL;
        transpose_w_kernel<<<(n + 255) / 256, 256>>>(w_s1, w_s2, w_s3);
    }
    // init out (c1..c3 regions) with bpl biases; conv kernels atomicAdd
    init_out_kernel<<<(64 * 224 + 255) / 256, 256>>>(b_pl1, b_pl2, b_pl3, out);

    float* wT;
    cudaGetSymbolAddress((void**)&wT, g_wT);

    // L1: H=64 W=128, base 0   -> 64 * 8 * 8 = 4096 blocks
    conv_level_kernel<64, 128, 0><<<64 * 8 * 8, 256>>>(
        p2, wT + 0 * KWEL, b_s1, w_t1, b_t1, w_pl1, out);
    // L2: H=32 W=64, base 128  -> 64 * 4 * 4 = 1024 blocks
    conv_level_kernel<32, 64, 128><<<64 * 4 * 4, 256>>>(
        p3, wT + 1 * KWEL, b_s2, w_t2, b_t2, w_pl2, out);
    // L3: H=16 W=32, base 192  -> 64 * 2 * 2 = 256 blocks
    conv_level_kernel<16, 32, 192><<<64 * 2 * 2, 256>>>(
        p4, wT + 2 * KWEL, b_s3, w_t3, b_t3, w_pl3, out);
    // p5 path, base 224
    p5_kernel<<<64, 256>>>(p5, w_t4, b_t4, w_pl4, b_pl4, out);
}

// round 4
// speedup vs baseline: 10.2106x; 3.5187x over previous
#include <cuda_runtime.h>
#include <cuda_fp16.h>
#include <cstdint>

// ---------------------------------------------------------------------------
// FPN head via legacy tensor cores (mma.sync m16n8k16 f16, fp32 accum).
//   D[o=128][n=positions] = sum_k W[o][k] * X[k][n],  k=(dy,dx,c) per level.
// tcgen05 is unavailable (harness PTX targets sm_103 w/o 'a'), so use the
// family-safe HMMA path with register accumulators.
// B staged per 32-ch chunk WITH halo (serves all 9 taps); A pre-converted to
// fp16 in the exact smem image (pitch 40 f16) and cp.async double-buffered.
// Epilogue fused: bias + ReLU + tidy dot(w_t) + column pooling.
// Output: [64, 240] fp32  (c1:128 | c2:64 | c3:32 | c4:16)
// ---------------------------------------------------------------------------

typedef unsigned int u32;

#define ACH_H 5120                       // halves per A chunk (128 o x 40)
__device__ __half g_wA[3 * 36 * ACH_H];  // prepped fp16 weights, padded pitch

// ---- PTX helpers ----------------------------------------------------------
__device__ __forceinline__ u32 smem_u32(const void* p) {
    u32 a;
    asm("{ .reg .u64 t; cvta.to.shared.u64 t, %1; cvt.u32.u64 %0, t; }"
        : "=r"(a) : "l"(p));
    return a;
}
__device__ __forceinline__ void cp16(u32 dst, const void* src) {
    asm volatile("cp.async.cg.shared.global [%0], [%1], 16;"
                 :: "r"(dst), "l"(src));
}
#define CP_COMMIT() asm volatile("cp.async.commit_group;")
#define CP_WAIT0()  asm volatile("cp.async.wait_group 0;")

__device__ __forceinline__ void ldm_x4(u32* r, u32 addr) {
    asm volatile("ldmatrix.sync.aligned.m8n8.x4.shared.b16 {%0,%1,%2,%3}, [%4];"
                 : "=r"(r[0]), "=r"(r[1]), "=r"(r[2]), "=r"(r[3]) : "r"(addr));
}
__device__ __forceinline__ void ldm_x2(u32& b0, u32& b1, u32 addr) {
    asm volatile("ldmatrix.sync.aligned.m8n8.x2.shared.b16 {%0,%1}, [%2];"
                 : "=r"(b0), "=r"(b1) : "r"(addr));
}
__device__ __forceinline__ void mma16816(float* d, const u32* a, u32 b0, u32 b1) {
    asm volatile(
        "mma.sync.aligned.m16n8k16.row.col.f32.f16.f16.f32 "
        "{%0,%1,%2,%3}, {%4,%5,%6,%7}, {%8,%9}, {%0,%1,%2,%3};"
        : "+f"(d[0]), "+f"(d[1]), "+f"(d[2]), "+f"(d[3])
        : "r"(a[0]), "r"(a[1]), "r"(a[2]), "r"(a[3]), "r"(b0), "r"(b1));
}

// ---- weight prep: w[o][c][tap] fp32 -> fp16 chunk images ------------------
// chunk gi = (c>>5)*9 + tap ; halves addr = ((l*36+gi)*128 + o)*40 + (c&31)
__global__ void prep_wA_kernel(const float* __restrict__ w1,
                               const float* __restrict__ w2,
                               const float* __restrict__ w3) {
    int i = blockIdx.x * 256 + threadIdx.x;
    if (i >= 3 * 147456) return;
    int l = i / 147456;
    int rr = i % 147456;
    int o = rr / 1152;
    int r2 = rr % 1152;
    int c = r2 / 9;
    int tap = r2 % 9;
    const float* src = (l == 0) ? w1 : (l == 1) ? w2 : w3;
    int gi = (c >> 5) * 9 + tap;
    g_wA[((l * 36 + gi) * 128 + o) * 40 + (c & 31)] = __float2half_rn(src[rr]);
}

// ---- out init: bpl bias for c1..c3 regions --------------------------------
__global__ void init_out_kernel(const float* __restrict__ bpl1,
                                const float* __restrict__ bpl2,
                                const float* __restrict__ bpl3,
                                float* __restrict__ out) {
    int i = blockIdx.x * blockDim.x + threadIdx.x;
    if (i >= 64 * 224) return;
    int j = i % 224;
    out[(i / 224) * 240 + j] = (j < 128) ? bpl1[0] : (j < 192) ? bpl2[0] : bpl3[0];
}

// ---- fused HMMA conv + epilogue -------------------------------------------
// Block: 256 threads. warpm = warp&3 (32 o each), warpn = warp>>2 (64 n each).
// Tile: 128 positions = R rows x W cols. SMEM: sCol@0, A(2x10240B)@512,
// B @20992: [(R+2)*(W+2) positions][40 f16] n-major, 16B-block XOR swizzle.
template <int H, int W, int LW, int R, int BASE>
__global__ void __launch_bounds__(256, 2)
conv_mma_kernel(const float* __restrict__ x,      // [64,128,H,W]
                const __half* __restrict__ wA,    // level slice of g_wA
                const float* __restrict__ bs,     // [128]
                const float* __restrict__ wt,     // [128]
                const float* __restrict__ bt,     // [1]
                const float* __restrict__ wpl,    // [H]
                float* __restrict__ out) {
    constexpr int NW = W + 2;
    constexpr int NP = (R + 2) * NW;
    constexpr int A_OFF = 512;
    constexpr int B_OFF = 20992;

    extern __shared__ char smem[];
    float* sCol = (float*)smem;
    const u32 smu = smem_u32(smem);

    const int tid = threadIdx.x;
    const int warp = tid >> 5;
    const int lane = tid & 31;
    const int warpm = warp & 3;
    const int warpn = warp >> 2;

    const int TPH = H / R;
    const int b = blockIdx.x / TPH;
    const int h0 = (blockIdx.x % TPH) * R;
    const float* xb = x + (size_t)b * 128 * H * W;

    if (tid < 128) sCol[tid] = 0.f;

    float d[2][8][4];
#pragma unroll
    for (int mi = 0; mi < 2; mi++)
#pragma unroll
        for (int nj = 0; nj < 8; nj++)
#pragma unroll
            for (int q = 0; q < 4; q++) d[mi][nj][q] = 0.f;

    // prefetch A chunk 0
    {
        const char* src = (const char*)wA;
        for (int i = tid; i < 640; i += 256) cp16(smu + A_OFF + i * 16, src + i * 16);
        CP_COMMIT();
    }

    for (int gi = 0; gi < 36; gi++) {
        const int cc = gi / 9;
        const int tap = gi - cc * 9;
        const int dy = tap / 3;
        const int dx = tap - dy * 3;

        if (tap == 0) {
            __syncthreads();  // prior taps' ldmatrix must finish before restage
            // stage B: 32 channels x NP halo positions, fp16 pairs, swizzled
            const int c0ch = cc * 32;
            for (int j = tid; j < 16 * NP; j += 256) {
                int cp = j / NP;
                int p = j - cp * NP;
                int r = p / NW;
                int w = p - r * NW;
                int hin = h0 + r - 1;
                int gw = w - 1;
                float v0 = 0.f, v1 = 0.f;
                if (hin >= 0 && hin < H && (unsigned)gw < (unsigned)W) {
                    const float* bp = xb + ((size_t)(c0ch + 2 * cp) * H + hin) * W + gw;
                    v0 = bp[0];
                    v1 = bp[H * W];
                }
                __half2 hv = __floats2half2_rn(v0, v1);
                int word = p * 20 + (((cp >> 2) ^ (p & 3)) << 2) + (cp & 3);
                *(__half2*)(smem + B_OFF + word * 4) = hv;
            }
        }
        CP_WAIT0();
        __syncthreads();
        if (gi + 1 < 36) {
            const char* src = (const char*)wA + (size_t)(gi + 1) * 10240;
            u32 dst = smu + A_OFF + ((gi + 1) & 1) * 10240;
            for (int i = tid; i < 640; i += 256) cp16(dst + i * 16, src + i * 16);
            CP_COMMIT();
        }

        const u32 abase = smu + A_OFF + (gi & 1) * 10240;
        const u32 bbase = smu + B_OFF;
#pragma unroll
        for (int ks = 0; ks < 2; ks++) {
            u32 a[2][4];
#pragma unroll
            for (int mi = 0; mi < 2; mi++) {
                int row = warpm * 32 + mi * 16 + (lane & 7) + ((lane >> 3) & 1) * 8;
                ldm_x4(a[mi], abase + row * 80 + ks * 32 + (lane >> 4) * 16);
            }
#pragma unroll
            for (int nj = 0; nj < 8; nj++) {
                int ng = warpn * 64 + nj * 8;
                int trow = ng >> LW;
                int tcol = ng & (W - 1);
                int p = (trow + dy) * NW + tcol + dx + (lane & 7);
                int kb = ks * 2 + ((lane >> 3) & 1);
                u32 b0, b1;
                ldm_x2(b0, b1, bbase + p * 80 + ((kb ^ (p & 3)) << 4));
                mma16816(d[0][nj], a[0], b0, b1);
                mma16816(d[1][nj], a[1], b0, b1);
            }
        }
    }

    // ---- epilogue: bias + ReLU + dot(w_t), reduce, pool -------------------
    const int g = lane >> 2;
    const int tid4 = lane & 3;
    float bsv[2][2], wtv[2][2];
#pragma unroll
    for (int mi = 0; mi < 2; mi++)
#pragma unroll
        for (int hh = 0; hh < 2; hh++) {
            int o = warpm * 32 + mi * 16 + hh * 8 + g;
            bsv[mi][hh] = bs[o];
            wtv[mi][hh] = wt[o];
        }
#pragma unroll
    for (int nj = 0; nj < 8; nj++) {
        float v0 = 0.f, v1 = 0.f;
#pragma unroll
        for (int mi = 0; mi < 2; mi++) {
            v0 += fmaxf(d[mi][nj][0] + bsv[mi][0], 0.f) * wtv[mi][0]
                + fmaxf(d[mi][nj][2] + bsv[mi][1], 0.f) * wtv[mi][1];
            v1 += fmaxf(d[mi][nj][1] + bsv[mi][0], 0.f) * wtv[mi][0]
                + fmaxf(d[mi][nj][3] + bsv[mi][1], 0.f) * wtv[mi][1];
        }
        v0 += __shfl_xor_sync(0xffffffffu, v0, 4);
        v0 += __shfl_xor_sync(0xffffffffu, v0, 8);
        v0 += __shfl_xor_sync(0xffffffffu, v0, 16);
        v1 += __shfl_xor_sync(0xffffffffu, v1, 4);
        v1 += __shfl_xor_sync(0xffffffffu, v1, 8);
        v1 += __shfl_xor_sync(0xffffffffu, v1, 16);
        if (lane < 4) {
            int n = warpn * 64 + nj * 8 + tid4 * 2;
            atomicAdd(&sCol[n], v0);
            atomicAdd(&sCol[n + 1], v1);
        }
    }
    __syncthreads();

    if (tid < W) {
        const float btv = bt[0];
        float s = 0.f;
#pragma unroll
        for (int r = 0; r < R; r++)
            s += wpl[h0 + r] * (sCol[r * W + tid] + btv);
        atomicAdd(&out[b * 240 + BASE + tid], s);
    }
}

// ---- p5 path: tidy 1x1 (512->1) + pool over h=8, memory bound -------------
__global__ void p5_kernel(const float* __restrict__ p5,
                          const float* __restrict__ wt,   // [512]
                          const float* __restrict__ bt,   // [1]
                          const float* __restrict__ wpl,  // [8]
                          const float* __restrict__ bpl,  // [1]
                          float* __restrict__ out) {
    const int b = blockIdx.x;
    const int tid = threadIdx.x;
    const int w = tid & 15;
    const int g = tid >> 4;
    __shared__ float red[256];
    __shared__ float spl[8];
    if (tid < 8) spl[tid] = wpl[tid];
    __syncthreads();

    const float* pb = p5 + (size_t)b * 512 * 8 * 16;
    float accv = 0.f;
    for (int c = g; c < 512; c += 16) {
        float wc = wt[c];
        const float* row = pb + (size_t)c * 8 * 16 + w;
#pragma unroll
        for (int h = 0; h < 8; h++)
            accv = fmaf(wc * spl[h], row[h * 16], accv);
    }
    red[tid] = accv;
    __syncthreads();
    if (tid < 16) {
        float s = 0.f;
#pragma unroll
        for (int gg = 0; gg < 16; gg++) s += red[gg * 16 + tid];
        float sumpl = 0.f;
#pragma unroll
        for (int h = 0; h < 8; h++) sumpl += spl[h];
        out[b * 240 + 224 + tid] = s + bt[0] * sumpl + bpl[0];
    }
}

// ---------------------------------------------------------------------------
extern "C" void kernel_launch(void* const* d_in, const int* in_sizes, int n_in,
                              void* d_out, int out_size) {
    const float* p2 = (const float*)d_in[0];
    const float* p3 = (const float*)d_in[1];
    const float* p4 = (const float*)d_in[2];
    const float* p5 = (const float*)d_in[3];
    const float* w_s1 = (const float*)d_in[4];
    const float* b_s1 = (const float*)d_in[5];
    const float* w_s2 = (const float*)d_in[6];
    const float* b_s2 = (const float*)d_in[7];
    const float* w_s3 = (const float*)d_in[8];
    const float* b_s3 = (const float*)d_in[9];
    const float* w_t1 = (const float*)d_in[10];
    const float* b_t1 = (const float*)d_in[11];
    const float* w_t2 = (const float*)d_in[12];
    const float* b_t2 = (const float*)d_in[13];
    const float* w_t3 = (const float*)d_in[14];
    const float* b_t3 = (const float*)d_in[15];
    const float* w_t4 = (const float*)d_in[16];
    const float* b_t4 = (const float*)d_in[17];
    const float* w_pl1 = (const float*)d_in[18];
    const float* b_pl1 = (const float*)d_in[19];
    const float* w_pl2 = (const float*)d_in[20];
    const float* b_pl2 = (const float*)d_in[21];
    const float* w_pl3 = (const float*)d_in[22];
    const float* b_pl3 = (const float*)d_in[23];
    const float* w_pl4 = (const float*)d_in[24];
    const float* b_pl4 = (const float*)d_in[25];
    float* out = (float*)d_out;

    prep_wA_kernel<<<(3 * 147456 + 255) / 256, 256>>>(w_s1, w_s2, w_s3);
    init_out_kernel<<<(64 * 224 + 255) / 256, 256>>>(b_pl1, b_pl2, b_pl3, out);

    __half* wAd;
    cudaGetSymbolAddress((void**)&wAd, g_wA);

    // dynamic smem: 20992 + NP*80 bytes
    const int sm1 = 20992 + (1 + 2) * 130 * 80;  // 52192
    const int sm2 = 20992 + (2 + 2) * 66 * 80;   // 42112
    const int sm3 = 20992 + (4 + 2) * 34 * 80;   // 37312
    cudaFuncSetAttribute(conv_mma_kernel<64, 128, 7, 1, 0>,
                         cudaFuncAttributeMaxDynamicSharedMemorySize, sm1);
    cudaFuncSetAttribute(conv_mma_kernel<32, 64, 6, 2, 128>,
                         cudaFuncAttributeMaxDynamicSharedMemorySize, sm2);
    cudaFuncSetAttribute(conv_mma_kernel<16, 32, 5, 4, 192>,
                         cudaFuncAttributeMaxDynamicSharedMemorySize, sm3);

    conv_mma_kernel<64, 128, 7, 1, 0><<<64 * 64, 256, sm1>>>(
        p2, wAd + 0 * 36 * ACH_H, b_s1, w_t1, b_t1, w_pl1, out);
    conv_mma_kernel<32, 64, 6, 2, 128><<<64 * 16, 256, sm2>>>(
        p3, wAd + 1 * 36 * ACH_H, b_s2, w_t2, b_t2, w_pl2, out);
    conv_mma_kernel<16, 32, 5, 4, 192><<<64 * 4, 256, sm3>>>(
        p4, wAd + 2 * 36 * ACH_H, b_s3, w_t3, b_t3, w_pl3, out);
    p5_kernel<<<64, 256>>>(p5, w_t4, b_t4, w_pl4, b_pl4, out);
}

// round 5
// speedup vs baseline: 11.1214x; 1.0892x over previous
#include <cuda_runtime.h>
#include <cuda_fp16.h>
#include <cstdint>

// ---------------------------------------------------------------------------
// FPN head via legacy tensor cores (mma.sync m16n8k16 f16, fp32 accum).
// R5: 256-position tiles (128 o x 256 n per block), warps 2m x 4n, B loads
// via ldmatrix.x4 (2 n-tiles per instr). 1.0 L1-wavefront per MMA (was 1.5).
// Output: [64, 240] fp32  (c1:128 | c2:64 | c3:32 | c4:16)
// ---------------------------------------------------------------------------

typedef unsigned int u32;

#define ACH_H 5120                       // halves per A chunk (128 o x 40)
__device__ __half g_wA[3 * 36 * ACH_H];  // prepped fp16 weights, padded pitch

// ---- PTX helpers ----------------------------------------------------------
__device__ __forceinline__ u32 smem_u32(const void* p) {
    u32 a;
    asm("{ .reg .u64 t; cvta.to.shared.u64 t, %1; cvt.u32.u64 %0, t; }"
        : "=r"(a) : "l"(p));
    return a;
}
__device__ __forceinline__ void cp16(u32 dst, const void* src) {
    asm volatile("cp.async.cg.shared.global [%0], [%1], 16;"
                 :: "r"(dst), "l"(src));
}
#define CP_COMMIT() asm volatile("cp.async.commit_group;")
#define CP_WAIT0()  asm volatile("cp.async.wait_group 0;")

__device__ __forceinline__ void ldm_x4(u32* r, u32 addr) {
    asm volatile("ldmatrix.sync.aligned.m8n8.x4.shared.b16 {%0,%1,%2,%3}, [%4];"
                 : "=r"(r[0]), "=r"(r[1]), "=r"(r[2]), "=r"(r[3]) : "r"(addr));
}
__device__ __forceinline__ void mma16816(float* d, const u32* a, u32 b0, u32 b1) {
    asm volatile(
        "mma.sync.aligned.m16n8k16.row.col.f32.f16.f16.f32 "
        "{%0,%1,%2,%3}, {%4,%5,%6,%7}, {%8,%9}, {%0,%1,%2,%3};"
        : "+f"(d[0]), "+f"(d[1]), "+f"(d[2]), "+f"(d[3])
        : "r"(a[0]), "r"(a[1]), "r"(a[2]), "r"(a[3]), "r"(b0), "r"(b1));
}

// ---- weight prep: w[o][c][tap] fp32 -> fp16 chunk images ------------------
// chunk gi = (c>>5)*9 + tap ; halves addr = ((l*36+gi)*128 + o)*40 + (c&31)
__global__ void prep_wA_kernel(const float* __restrict__ w1,
                               const float* __restrict__ w2,
                               const float* __restrict__ w3) {
    int i = blockIdx.x * 256 + threadIdx.x;
    if (i >= 3 * 147456) return;
    int l = i / 147456;
    int rr = i % 147456;
    int o = rr / 1152;
    int r2 = rr % 1152;
    int c = r2 / 9;
    int tap = r2 % 9;
    const float* src = (l == 0) ? w1 : (l == 1) ? w2 : w3;
    int gi = (c >> 5) * 9 + tap;
    g_wA[((l * 36 + gi) * 128 + o) * 40 + (c & 31)] = __float2half_rn(src[rr]);
}

// ---- out init: bpl bias for c1..c3 regions --------------------------------
__global__ void init_out_kernel(const float* __restrict__ bpl1,
                                const float* __restrict__ bpl2,
                                const float* __restrict__ bpl3,
                                float* __restrict__ out) {
    int i = blockIdx.x * blockDim.x + threadIdx.x;
    if (i >= 64 * 224) return;
    int j = i % 224;
    out[(i / 224) * 240 + j] = (j < 128) ? bpl1[0] : (j < 192) ? bpl2[0] : bpl3[0];
}

// ---- fused HMMA conv + epilogue -------------------------------------------
// Block: 256 threads = 8 warps as 2(m) x 4(n). Warp tile: 64 o x 64 n.
// Block tile: 128 o x 256 n = R rows x W cols of positions.
// SMEM: sCol(256f)@0, A(2x10240B)@1024, B@21504:
//   [(R+2)*(W+2) positions][40 f16] n-major, 16B-block XOR swizzle.
template <int H, int W, int LW, int R, int BASE>
__global__ void __launch_bounds__(256, 1)
conv_mma_kernel(const float* __restrict__ x,      // [64,128,H,W]
                const __half* __restrict__ wA,    // level slice of g_wA
                const float* __restrict__ bs,     // [128]
                const float* __restrict__ wt,     // [128]
                const float* __restrict__ bt,     // [1]
                const float* __restrict__ wpl,    // [H]
                float* __restrict__ out) {
    constexpr int NW = W + 2;
    constexpr int NP = (R + 2) * NW;
    constexpr int A_OFF = 1024;
    constexpr int B_OFF = 21504;

    extern __shared__ char smem[];
    float* sCol = (float*)smem;
    const u32 smu = smem_u32(smem);

    const int tid = threadIdx.x;
    const int warp = tid >> 5;
    const int lane = tid & 31;
    const int warpm = warp & 1;
    const int warpn = warp >> 1;

    const int TPH = H / R;
    const int b = blockIdx.x / TPH;
    const int h0 = (blockIdx.x % TPH) * R;
    const float* xb = x + (size_t)b * 128 * H * W;

    sCol[tid] = 0.f;

    float d[4][8][4];
#pragma unroll
    for (int mi = 0; mi < 4; mi++)
#pragma unroll
        for (int nj = 0; nj < 8; nj++)
#pragma unroll
            for (int q = 0; q < 4; q++) d[mi][nj][q] = 0.f;

    // prefetch A chunk 0
    {
        const char* src = (const char*)wA;
        for (int i = tid; i < 640; i += 256) cp16(smu + A_OFF + i * 16, src + i * 16);
        CP_COMMIT();
    }

    const u32 bbase = smu + B_OFF;
    for (int gi = 0; gi < 36; gi++) {
        const int cc = gi / 9;
        const int tap = gi - cc * 9;
        const int dy = tap / 3;
        const int dx = tap - dy * 3;

        if (tap == 0) {
            __syncthreads();  // prior taps' ldmatrix must finish before restage
            // stage B: 32 channels x NP halo positions, fp16 pairs, swizzled.
            // cp = tid>>4 (channel pair group), p strided by 16 (coalesced).
            const int c0ch = cc * 32;
            const int cp = tid >> 4;
            const int swc = ((cp >> 2) << 2) + (cp & 3);  // cp part of swizzle
            for (int p = tid & 15; p < NP; p += 16) {
                int r = p / NW;
                int w = p - r * NW;
                int hin = h0 + r - 1;
                int gw = w - 1;
                float v0 = 0.f, v1 = 0.f;
                if (hin >= 0 && hin < H && (unsigned)gw < (unsigned)W) {
                    const float* bp = xb + ((size_t)(c0ch + 2 * cp) * H + hin) * W + gw;
                    v0 = bp[0];
                    v1 = bp[H * W];
                }
                __half2 hv = __floats2half2_rn(v0, v1);
                int word = p * 20 + ((((cp >> 2) ^ (p & 3)) << 2)) + (cp & 3);
                *(__half2*)(smem + B_OFF + word * 4) = hv;
            }
        }
        CP_WAIT0();
        __syncthreads();
        if (gi + 1 < 36) {
            const char* src = (const char*)wA + (size_t)(gi + 1) * 10240;
            u32 dst = smu + A_OFF + ((gi + 1) & 1) * 10240;
            for (int i = tid; i < 640; i += 256) cp16(dst + i * 16, src + i * 16);
            CP_COMMIT();
        }

        const u32 abase = smu + A_OFF + (gi & 1) * 10240;
#pragma unroll
        for (int ks = 0; ks < 2; ks++) {
            u32 a[4][4];
#pragma unroll
            for (int mi = 0; mi < 4; mi++) {
                int row = warpm * 64 + mi * 16 + (lane & 7) + ((lane >> 3) & 1) * 8;
                ldm_x4(a[mi], abase + row * 80 + ks * 32 + (lane >> 4) * 16);
            }
#pragma unroll
            for (int njp = 0; njp < 8; njp += 2) {
                // ldmatrix.x4: tiles {nj,kb0},{nj,kb1},{nj+1,kb0},{nj+1,kb1}
                int ng = warpn * 64 + njp * 8 + (lane >> 4) * 8;
                int trow = ng >> LW;
                int tcol = ng & (W - 1);
                int p = (trow + dy) * NW + tcol + dx + (lane & 7);
                int kb = ks * 2 + ((lane >> 3) & 1);
                u32 bf[4];
                ldm_x4(bf, bbase + p * 80 + ((kb ^ (p & 3)) << 4));
#pragma unroll
                for (int mi = 0; mi < 4; mi++) {
                    mma16816(d[mi][njp], a[mi], bf[0], bf[1]);
                    mma16816(d[mi][njp + 1], a[mi], bf[2], bf[3]);
                }
            }
        }
    }

    // ---- epilogue: bias + ReLU + dot(w_t), reduce, pool -------------------
    const int g = lane >> 2;
    const int tid4 = lane & 3;
    float bsv[4][2], wtv[4][2];
#pragma unroll
    for (int mi = 0; mi < 4; mi++)
#pragma unroll
        for (int hh = 0; hh < 2; hh++) {
            int o = warpm * 64 + mi * 16 + hh * 8 + g;
            bsv[mi][hh] = bs[o];
            wtv[mi][hh] = wt[o];
        }
#pragma unroll
    for (int nj = 0; nj < 8; nj++) {
        float v0 = 0.f, v1 = 0.f;
#pragma unroll
        for (int mi = 0; mi < 4; mi++) {
            v0 += fmaxf(d[mi][nj][0] + bsv[mi][0], 0.f) * wtv[mi][0]
                + fmaxf(d[mi][nj][2] + bsv[mi][1], 0.f) * wtv[mi][1];
            v1 += fmaxf(d[mi][nj][1] + bsv[mi][0], 0.f) * wtv[mi][0]
                + fmaxf(d[mi][nj][3] + bsv[mi][1], 0.f) * wtv[mi][1];
        }
        v0 += __shfl_xor_sync(0xffffffffu, v0, 4);
        v0 += __shfl_xor_sync(0xffffffffu, v0, 8);
        v0 += __shfl_xor_sync(0xffffffffu, v0, 16);
        v1 += __shfl_xor_sync(0xffffffffu, v1, 4);
        v1 += __shfl_xor_sync(0xffffffffu, v1, 8);
        v1 += __shfl_xor_sync(0xffffffffu, v1, 16);
        if (lane < 4) {
            int n = warpn * 64 + nj * 8 + tid4 * 2;
            atomicAdd(&sCol[n], v0);
            atomicAdd(&sCol[n + 1], v1);
        }
    }
    __syncthreads();

    if (tid < W) {
        const float btv = bt[0];
        float s = 0.f;
#pragma unroll
        for (int r = 0; r < R; r++)
            s += wpl[h0 + r] * (sCol[r * W + tid] + btv);
        atomicAdd(&out[b * 240 + BASE + tid], s);
    }
}

// ---- p5 path: tidy 1x1 (512->1) + pool over h=8, memory bound -------------
__global__ void p5_kernel(const float* __restrict__ p5,
                          const float* __restrict__ wt,   // [512]
                          const float* __restrict__ bt,   // [1]
                          const float* __restrict__ wpl,  // [8]
                          const float* __restrict__ bpl,  // [1]
                          float* __restrict__ out) {
    const int b = blockIdx.x;
    const int tid = threadIdx.x;
    const int w = tid & 15;
    const int g = tid >> 4;
    __shared__ float red[256];
    __shared__ float spl[8];
    if (tid < 8) spl[tid] = wpl[tid];
    __syncthreads();

    const float* pb = p5 + (size_t)b * 512 * 8 * 16;
    float accv = 0.f;
    for (int c = g; c < 512; c += 16) {
        float wc = wt[c];
        const float* row = pb + (size_t)c * 8 * 16 + w;
#pragma unroll
        for (int h = 0; h < 8; h++)
            accv = fmaf(wc * spl[h], row[h * 16], accv);
    }
    red[tid] = accv;
    __syncthreads();
    if (tid < 16) {
        float s = 0.f;
#pragma unroll
        for (int gg = 0; gg < 16; gg++) s += red[gg * 16 + tid];
        float sumpl = 0.f;
#pragma unroll
        for (int h = 0; h < 8; h++) sumpl += spl[h];
        out[b * 240 + 224 + tid] = s + bt[0] * sumpl + bpl[0];
    }
}

// ---------------------------------------------------------------------------
extern "C" void kernel_launch(void* const* d_in, const int* in_sizes, int n_in,
                              void* d_out, int out_size) {
    const float* p2 = (const float*)d_in[0];
    const float* p3 = (const float*)d_in[1];
    const float* p4 = (const float*)d_in[2];
    const float* p5 = (const float*)d_in[3];
    const float* w_s1 = (const float*)d_in[4];
    const float* b_s1 = (const float*)d_in[5];
    const float* w_s2 = (const float*)d_in[6];
    const float* b_s2 = (const float*)d_in[7];
    const float* w_s3 = (const float*)d_in[8];
    const float* b_s3 = (const float*)d_in[9];
    const float* w_t1 = (const float*)d_in[10];
    const float* b_t1 = (const float*)d_in[11];
    const float* w_t2 = (const float*)d_in[12];
    const float* b_t2 = (const float*)d_in[13];
    const float* w_t3 = (const float*)d_in[14];
    const float* b_t3 = (const float*)d_in[15];
    const float* w_t4 = (const float*)d_in[16];
    const float* b_t4 = (const float*)d_in[17];
    const float* w_pl1 = (const float*)d_in[18];
    const float* b_pl1 = (const float*)d_in[19];
    const float* w_pl2 = (const float*)d_in[20];
    const float* b_pl2 = (const float*)d_in[21];
    const float* w_pl3 = (const float*)d_in[22];
    const float* b_pl3 = (const float*)d_in[23];
    const float* w_pl4 = (const float*)d_in[24];
    const float* b_pl4 = (const float*)d_in[25];
    float* out = (float*)d_out;

    prep_wA_kernel<<<(3 * 147456 + 255) / 256, 256>>>(w_s1, w_s2, w_s3);
    init_out_kernel<<<(64 * 224 + 255) / 256, 256>>>(b_pl1, b_pl2, b_pl3, out);

    __half* wAd;
    cudaGetSymbolAddress((void**)&wAd, g_wA);

    // dynamic smem: 21504 + NP*80 bytes
    const int sm1 = 21504 + (2 + 2) * 130 * 80;  // 63104
    const int sm2 = 21504 + (4 + 2) * 66 * 80;   // 53184
    const int sm3 = 21504 + (8 + 2) * 34 * 80;   // 48704
    cudaFuncSetAttribute(conv_mma_kernel<64, 128, 7, 2, 0>,
                         cudaFuncAttributeMaxDynamicSharedMemorySize, sm1);
    cudaFuncSetAttribute(conv_mma_kernel<32, 64, 6, 4, 128>,
                         cudaFuncAttributeMaxDynamicSharedMemorySize, sm2);
    cudaFuncSetAttribute(conv_mma_kernel<16, 32, 5, 8, 192>,
                         cudaFuncAttributeMaxDynamicSharedMemorySize, sm3);

    conv_mma_kernel<64, 128, 7, 2, 0><<<64 * 32, 256, sm1>>>(
        p2, wAd + 0 * 36 * ACH_H, b_s1, w_t1, b_t1, w_pl1, out);
    conv_mma_kernel<32, 64, 6, 4, 128><<<64 * 8, 256, sm2>>>(
        p3, wAd + 1 * 36 * ACH_H, b_s2, w_t2, b_t2, w_pl2, out);
    conv_mma_kernel<16, 32, 5, 8, 192><<<64 * 2, 256, sm3>>>(
        p4, wAd + 2 * 36 * ACH_H, b_s3, w_t3, b_t3, w_pl3, out);
    p5_kernel<<<64, 256>>>(p5, w_t4, b_t4, w_pl4, b_pl4, out);
}

// round 6
// speedup vs baseline: 11.7037x; 1.0524x over previous
#include <cuda_runtime.h>
#include <cuda_fp16.h>
#include <cstdint>

// ---------------------------------------------------------------------------
// FPN head via legacy tensor cores (mma.sync m16n8k16 f16, fp32 accum).
// R6: same 128o x 256n block tile as R5 but 512 threads = 16 warps (2m x 8n,
// warp tile 64o x 32n, 64 accs) -> 2x warps/SMSP for latency hiding.
// Output: [64, 240] fp32  (c1:128 | c2:64 | c3:32 | c4:16)
// ---------------------------------------------------------------------------

typedef unsigned int u32;

#define ACH_H 5120                       // halves per A chunk (128 o x 40)
__device__ __half g_wA[3 * 36 * ACH_H];  // prepped fp16 weights, padded pitch

// ---- PTX helpers ----------------------------------------------------------
__device__ __forceinline__ u32 smem_u32(const void* p) {
    u32 a;
    asm("{ .reg .u64 t; cvta.to.shared.u64 t, %1; cvt.u32.u64 %0, t; }"
        : "=r"(a) : "l"(p));
    return a;
}
__device__ __forceinline__ void cp16(u32 dst, const void* src) {
    asm volatile("cp.async.cg.shared.global [%0], [%1], 16;"
                 :: "r"(dst), "l"(src));
}
#define CP_COMMIT() asm volatile("cp.async.commit_group;")
#define CP_WAIT0()  asm volatile("cp.async.wait_group 0;")

__device__ __forceinline__ void ldm_x4(u32* r, u32 addr) {
    asm volatile("ldmatrix.sync.aligned.m8n8.x4.shared.b16 {%0,%1,%2,%3}, [%4];"
                 : "=r"(r[0]), "=r"(r[1]), "=r"(r[2]), "=r"(r[3]) : "r"(addr));
}
__device__ __forceinline__ void mma16816(float* d, const u32* a, u32 b0, u32 b1) {
    asm volatile(
        "mma.sync.aligned.m16n8k16.row.col.f32.f16.f16.f32 "
        "{%0,%1,%2,%3}, {%4,%5,%6,%7}, {%8,%9}, {%0,%1,%2,%3};"
        : "+f"(d[0]), "+f"(d[1]), "+f"(d[2]), "+f"(d[3])
        : "r"(a[0]), "r"(a[1]), "r"(a[2]), "r"(a[3]), "r"(b0), "r"(b1));
}

// ---- weight prep: w[o][c][tap] fp32 -> fp16 chunk images ------------------
// chunk gi = (c>>5)*9 + tap ; halves addr = ((l*36+gi)*128 + o)*40 + (c&31)
__global__ void prep_wA_kernel(const float* __restrict__ w1,
                               const float* __restrict__ w2,
                               const float* __restrict__ w3) {
    int i = blockIdx.x * 256 + threadIdx.x;
    if (i >= 3 * 147456) return;
    int l = i / 147456;
    int rr = i % 147456;
    int o = rr / 1152;
    int r2 = rr % 1152;
    int c = r2 / 9;
    int tap = r2 % 9;
    const float* src = (l == 0) ? w1 : (l == 1) ? w2 : w3;
    int gi = (c >> 5) * 9 + tap;
    g_wA[((l * 36 + gi) * 128 + o) * 40 + (c & 31)] = __float2half_rn(src[rr]);
}

// ---- out init: bpl bias for c1..c3 regions --------------------------------
__global__ void init_out_kernel(const float* __restrict__ bpl1,
                                const float* __restrict__ bpl2,
                                const float* __restrict__ bpl3,
                                float* __restrict__ out) {
    int i = blockIdx.x * blockDim.x + threadIdx.x;
    if (i >= 64 * 224) return;
    int j = i % 224;
    out[(i / 224) * 240 + j] = (j < 128) ? bpl1[0] : (j < 192) ? bpl2[0] : bpl3[0];
}

// ---- fused HMMA conv + epilogue -------------------------------------------
// Block: 512 threads = 16 warps as 2(m) x 8(n). Warp tile: 64 o x 32 n.
// Block tile: 128 o x 256 n = R rows x W cols of positions.
// SMEM: sCol(256f)@0, A(2x10240B)@1024, B@21504:
//   [(R+2)*(W+2) positions][40 f16] n-major, 16B-block XOR swizzle.
template <int H, int W, int LW, int R, int BASE>
__global__ void __launch_bounds__(512, 1)
conv_mma_kernel(const float* __restrict__ x,      // [64,128,H,W]
                const __half* __restrict__ wA,    // level slice of g_wA
                const float* __restrict__ bs,     // [128]
                const float* __restrict__ wt,     // [128]
                const float* __restrict__ bt,     // [1]
                const float* __restrict__ wpl,    // [H]
                float* __restrict__ out) {
    constexpr int NW = W + 2;
    constexpr int NP = (R + 2) * NW;
    constexpr int A_OFF = 1024;
    constexpr int B_OFF = 21504;

    extern __shared__ char smem[];
    float* sCol = (float*)smem;
    const u32 smu = smem_u32(smem);

    const int tid = threadIdx.x;
    const int warp = tid >> 5;
    const int lane = tid & 31;
    const int warpm = warp & 1;
    const int warpn = warp >> 1;   // 0..7, each 32 n

    const int TPH = H / R;
    const int b = blockIdx.x / TPH;
    const int h0 = (blockIdx.x % TPH) * R;
    const float* xb = x + (size_t)b * 128 * H * W;

    if (tid < 256) sCol[tid] = 0.f;

    float d[4][4][4];
#pragma unroll
    for (int mi = 0; mi < 4; mi++)
#pragma unroll
        for (int nj = 0; nj < 4; nj++)
#pragma unroll
            for (int q = 0; q < 4; q++) d[mi][nj][q] = 0.f;

    // prefetch A chunk 0
    {
        const char* src = (const char*)wA;
        for (int i = tid; i < 640; i += 512) cp16(smu + A_OFF + i * 16, src + i * 16);
        CP_COMMIT();
    }

    const u32 bbase = smu + B_OFF;
    for (int gi = 0; gi < 36; gi++) {
        const int cc = gi / 9;
        const int tap = gi - cc * 9;
        const int dy = tap / 3;
        const int dx = tap - dy * 3;

        if (tap == 0) {
            __syncthreads();  // prior taps' ldmatrix must finish before restage
            // stage B: 32 channels x NP halo positions, fp16 pairs, swizzled.
            // cp = tid>>5 (channel pair group 0..15), p strided 32 (coalesced)
            const int c0ch = cc * 32;
            const int cp = tid >> 5;
            for (int p = tid & 31; p < NP; p += 32) {
                int r = p / NW;
                int w = p - r * NW;
                int hin = h0 + r - 1;
                int gw = w - 1;
                float v0 = 0.f, v1 = 0.f;
                if (hin >= 0 && hin < H && (unsigned)gw < (unsigned)W) {
                    const float* bp = xb + ((size_t)(c0ch + 2 * cp) * H + hin) * W + gw;
                    v0 = bp[0];
                    v1 = bp[H * W];
                }
                __half2 hv = __floats2half2_rn(v0, v1);
                int word = p * 20 + ((((cp >> 2) ^ (p & 3)) << 2)) + (cp & 3);
                *(__half2*)(smem + B_OFF + word * 4) = hv;
            }
        }
        CP_WAIT0();
        __syncthreads();
        if (gi + 1 < 36) {
            const char* src = (const char*)wA + (size_t)(gi + 1) * 10240;
            u32 dst = smu + A_OFF + ((gi + 1) & 1) * 10240;
            for (int i = tid; i < 640; i += 512) cp16(dst + i * 16, src + i * 16);
            CP_COMMIT();
        }

        const u32 abase = smu + A_OFF + (gi & 1) * 10240;
#pragma unroll
        for (int ks = 0; ks < 2; ks++) {
            u32 a[4][4];
#pragma unroll
            for (int mi = 0; mi < 4; mi++) {
                int row = warpm * 64 + mi * 16 + (lane & 7) + ((lane >> 3) & 1) * 8;
                ldm_x4(a[mi], abase + row * 80 + ks * 32 + (lane >> 4) * 16);
            }
#pragma unroll
            for (int njp = 0; njp < 4; njp += 2) {
                // ldmatrix.x4: tiles {nj,kb0},{nj,kb1},{nj+1,kb0},{nj+1,kb1}
                int ng = warpn * 32 + njp * 8 + (lane >> 4) * 8;
                int trow = ng >> LW;
                int tcol = ng & (W - 1);
                int p = (trow + dy) * NW + tcol + dx + (lane & 7);
                int kb = ks * 2 + ((lane >> 3) & 1);
                u32 bf[4];
                ldm_x4(bf, bbase + p * 80 + ((kb ^ (p & 3)) << 4));
#pragma unroll
                for (int mi = 0; mi < 4; mi++) {
                    mma16816(d[mi][njp], a[mi], bf[0], bf[1]);
                    mma16816(d[mi][njp + 1], a[mi], bf[2], bf[3]);
                }
            }
        }
    }

    // ---- epilogue: bias + ReLU + dot(w_t), reduce, pool -------------------
    const int g = lane >> 2;
    const int tid4 = lane & 3;
    float bsv[4][2], wtv[4][2];
#pragma unroll
    for (int mi = 0; mi < 4; mi++)
#pragma unroll
        for (int hh = 0; hh < 2; hh++) {
            int o = warpm * 64 + mi * 16 + hh * 8 + g;
            bsv[mi][hh] = bs[o];
            wtv[mi][hh] = wt[o];
        }
#pragma unroll
    for (int nj = 0; nj < 4; nj++) {
        float v0 = 0.f, v1 = 0.f;
#pragma unroll
        for (int mi = 0; mi < 4; mi++) {
            v0 += fmaxf(d[mi][nj][0] + bsv[mi][0], 0.f) * wtv[mi][0]
                + fmaxf(d[mi][nj][2] + bsv[mi][1], 0.f) * wtv[mi][1];
            v1 += fmaxf(d[mi][nj][1] + bsv[mi][0], 0.f) * wtv[mi][0]
                + fmaxf(d[mi][nj][3] + bsv[mi][1], 0.f) * wtv[mi][1];
        }
        v0 += __shfl_xor_sync(0xffffffffu, v0, 4);
        v0 += __shfl_xor_sync(0xffffffffu, v0, 8);
        v0 += __shfl_xor_sync(0xffffffffu, v0, 16);
        v1 += __shfl_xor_sync(0xffffffffu, v1, 4);
        v1 += __shfl_xor_sync(0xffffffffu, v1, 8);
        v1 += __shfl_xor_sync(0xffffffffu, v1, 16);
        if (lane < 4) {
            int n = warpn * 32 + nj * 8 + tid4 * 2;
            atomicAdd(&sCol[n], v0);
            atomicAdd(&sCol[n + 1], v1);
        }
    }
    __syncthreads();

    if (tid < W) {
        const float btv = bt[0];
        float s = 0.f;
#pragma unroll
        for (int r = 0; r < R; r++)
            s += wpl[h0 + r] * (sCol[r * W + tid] + btv);
        atomicAdd(&out[b * 240 + BASE + tid], s);
    }
}

// ---- p5 path: tidy 1x1 (512->1) + pool over h=8, memory bound -------------
__global__ void p5_kernel(const float* __restrict__ p5,
                          const float* __restrict__ wt,   // [512]
                          const float* __restrict__ bt,   // [1]
                          const float* __restrict__ wpl,  // [8]
                          const float* __restrict__ bpl,  // [1]
                          float* __restrict__ out) {
    const int b = blockIdx.x;
    const int tid = threadIdx.x;
    const int w = tid & 15;
    const int g = tid >> 4;
    __shared__ float red[256];
    __shared__ float spl[8];
    if (tid < 8) spl[tid] = wpl[tid];
    __syncthreads();

    const float* pb = p5 + (size_t)b * 512 * 8 * 16;
    float accv = 0.f;
    for (int c = g; c < 512; c += 16) {
        float wc = wt[c];
        const float* row = pb + (size_t)c * 8 * 16 + w;
#pragma unroll
        for (int h = 0; h < 8; h++)
            accv = fmaf(wc * spl[h], row[h * 16], accv);
    }
    red[tid] = accv;
    __syncthreads();
    if (tid < 16) {
        float s = 0.f;
#pragma unroll
        for (int gg = 0; gg < 16; gg++) s += red[gg * 16 + tid];
        float sumpl = 0.f;
#pragma unroll
        for (int h = 0; h < 8; h++) sumpl += spl[h];
        out[b * 240 + 224 + tid] = s + bt[0] * sumpl + bpl[0];
    }
}

// ---------------------------------------------------------------------------
extern "C" void kernel_launch(void* const* d_in, const int* in_sizes, int n_in,
                              void* d_out, int out_size) {
    const float* p2 = (const float*)d_in[0];
    const float* p3 = (const float*)d_in[1];
    const float* p4 = (const float*)d_in[2];
    const float* p5 = (const float*)d_in[3];
    const float* w_s1 = (const float*)d_in[4];
    const float* b_s1 = (const float*)d_in[5];
    const float* w_s2 = (const float*)d_in[6];
    const float* b_s2 = (const float*)d_in[7];
    const float* w_s3 = (const float*)d_in[8];
    const float* b_s3 = (const float*)d_in[9];
    const float* w_t1 = (const float*)d_in[10];
    const float* b_t1 = (const float*)d_in[11];
    const float* w_t2 = (const float*)d_in[12];
    const float* b_t2 = (const float*)d_in[13];
    const float* w_t3 = (const float*)d_in[14];
    const float* b_t3 = (const float*)d_in[15];
    const float* w_t4 = (const float*)d_in[16];
    const float* b_t4 = (const float*)d_in[17];
    const float* w_pl1 = (const float*)d_in[18];
    const float* b_pl1 = (const float*)d_in[19];
    const float* w_pl2 = (const float*)d_in[20];
    const float* b_pl2 = (const float*)d_in[21];
    const float* w_pl3 = (const float*)d_in[22];
    const float* b_pl3 = (const float*)d_in[23];
    const float* w_pl4 = (const float*)d_in[24];
    const float* b_pl4 = (const float*)d_in[25];
    float* out = (float*)d_out;

    prep_wA_kernel<<<(3 * 147456 + 255) / 256, 256>>>(w_s1, w_s2, w_s3);
    init_out_kernel<<<(64 * 224 + 255) / 256, 256>>>(b_pl1, b_pl2, b_pl3, out);

    __half* wAd;
    cudaGetSymbolAddress((void**)&wAd, g_wA);

    // dynamic smem: 21504 + NP*80 bytes
    const int sm1 = 21504 + (2 + 2) * 130 * 80;  // 63104
    const int sm2 = 21504 + (4 + 2) * 66 * 80;   // 53184
    const int sm3 = 21504 + (8 + 2) * 34 * 80;   // 48704
    cudaFuncSetAttribute(conv_mma_kernel<64, 128, 7, 2, 0>,
                         cudaFuncAttributeMaxDynamicSharedMemorySize, sm1);
    cudaFuncSetAttribute(conv_mma_kernel<32, 64, 6, 4, 128>,
                         cudaFuncAttributeMaxDynamicSharedMemorySize, sm2);
    cudaFuncSetAttribute(conv_mma_kernel<16, 32, 5, 8, 192>,
                         cudaFuncAttributeMaxDynamicSharedMemorySize, sm3);

    conv_mma_kernel<64, 128, 7, 2, 0><<<64 * 32, 512, sm1>>>(
        p2, wAd + 0 * 36 * ACH_H, b_s1, w_t1, b_t1, w_pl1, out);
    conv_mma_kernel<32, 64, 6, 4, 128><<<64 * 8, 512, sm2>>>(
        p3, wAd + 1 * 36 * ACH_H, b_s2, w_t2, b_t2, w_pl2, out);
    conv_mma_kernel<16, 32, 5, 8, 192><<<64 * 2, 512, sm3>>>(
        p4, wAd + 2 * 36 * ACH_H, b_s3, w_t3, b_t3, w_pl3, out);
    p5_kernel<<<64, 256>>>(p5, w_t4, b_t4, w_pl4, b_pl4, out);
}

// round 7
// speedup vs baseline: 14.1161x; 1.2061x over previous
#include <cuda_runtime.h>
#include <cuda_fp16.h>
#include <cstdint>

// ---------------------------------------------------------------------------
// FPN head via legacy tensor cores (mma.sync m16n8k16 f16, fp32 accum).
// R7: A (weights) in fragment-direct gmem layout loaded via LDG.128 (L1/L2
// cached, no smem, no cp.async) -> only 2 barriers per 32-ch chunk (8 total).
// Each chunk body = straight-line 9-tap MMA stream, free for ptxas scheduling.
// B staged in smem once per chunk with halo; fused epilogue as before.
// Output: [64, 240] fp32  (c1:128 | c2:64 | c3:32 | c4:16)
// ---------------------------------------------------------------------------

typedef unsigned int u32;

// A fragment image: [l][gi(36)][rg(8)][ks(2)][lane(32)] x uint4
__device__ uint4 g_wA[3 * 36 * 8 * 2 * 32];

// ---- PTX helpers ----------------------------------------------------------
__device__ __forceinline__ u32 smem_u32(const void* p) {
    u32 a;
    asm("{ .reg .u64 t; cvta.to.shared.u64 t, %1; cvt.u32.u64 %0, t; }"
        : "=r"(a) : "l"(p));
    return a;
}
__device__ __forceinline__ void ldm_x4(u32* r, u32 addr) {
    asm volatile("ldmatrix.sync.aligned.m8n8.x4.shared.b16 {%0,%1,%2,%3}, [%4];"
                 : "=r"(r[0]), "=r"(r[1]), "=r"(r[2]), "=r"(r[3]) : "r"(addr));
}
__device__ __forceinline__ void mma16816(float* d, const uint4 a, u32 b0, u32 b1) {
    asm volatile(
        "mma.sync.aligned.m16n8k16.row.col.f32.f16.f16.f32 "
        "{%0,%1,%2,%3}, {%4,%5,%6,%7}, {%8,%9}, {%0,%1,%2,%3};"
        : "+f"(d[0]), "+f"(d[1]), "+f"(d[2]), "+f"(d[3])
        : "r"(a.x), "r"(a.y), "r"(a.z), "r"(a.w), "r"(b0), "r"(b1));
}

// ---- weight prep: w[o][c][tap] fp32 -> A fragment image -------------------
// For (gi, rg, ks, lane, q): o = rg*16 + lane/4 + (q&1)*8,
//   k = ks*16 + (lane&3)*2 + (q>>1)*8, c = (gi/9)*32 + k, tap = gi%9.
// u32 = half2( w[o][c][tap], w[o][c+1][tap] ).
__global__ void prep_wA_kernel(const float* __restrict__ w1,
                               const float* __restrict__ w2,
                               const float* __restrict__ w3) {
    int i = blockIdx.x * 256 + threadIdx.x;          // one u32 each
    if (i >= 3 * 36 * 2048) return;
    int q    = i & 3;
    int lane = (i >> 2) & 31;
    int ks   = (i >> 7) & 1;
    int rg   = (i >> 8) & 7;
    int gi   = (i >> 11) % 36;
    int l    = i / (36 << 11);
    const float* src = (l == 0) ? w1 : (l == 1) ? w2 : w3;
    int o = rg * 16 + (lane >> 2) + (q & 1) * 8;
    int k = ks * 16 + (lane & 3) * 2 + (q >> 1) * 8;
    int c = (gi / 9) * 32 + k;
    int tap = gi % 9;
    __half2 hv = __floats2half2_rn(src[o * 1152 + c * 9 + tap],
                                   src[o * 1152 + (c + 1) * 9 + tap]);
    ((u32*)g_wA)[i] = *(u32*)&hv;
}

// ---- out init: bpl bias for c1..c3 regions --------------------------------
__global__ void init_out_kernel(const float* __restrict__ bpl1,
                                const float* __restrict__ bpl2,
                                const float* __restrict__ bpl3,
                                float* __restrict__ out) {
    int i = blockIdx.x * blockDim.x + threadIdx.x;
    if (i >= 64 * 224) return;
    int j = i % 224;
    out[(i / 224) * 240 + j] = (j < 128) ? bpl1[0] : (j < 192) ? bpl2[0] : bpl3[0];
}

// ---- fused HMMA conv + epilogue -------------------------------------------
// Block: 512 threads = 16 warps as 2(m) x 8(n). Warp tile: 64 o x 32 n.
// Block tile: 128 o x 256 n = R rows x W cols of positions.
// SMEM: sCol(256f)@0, B@1024: [(R+2)*(W+2) pos][40 f16], 16B-block XOR swizzle
template <int H, int W, int LW, int R, int BASE>
__global__ void __launch_bounds__(512, 1)
conv_mma_kernel(const float* __restrict__ x,      // [64,128,H,W]
                const uint4* __restrict__ wA,     // level slice of g_wA
                const float* __restrict__ bs,     // [128]
                const float* __restrict__ wt,     // [128]
                const float* __restrict__ bt,     // [1]
                const float* __restrict__ wpl,    // [H]
                float* __restrict__ out) {
    constexpr int NW = W + 2;
    constexpr int NP = (R + 2) * NW;
    constexpr int B_OFF = 1024;

    extern __shared__ char smem[];
    float* sCol = (float*)smem;
    const u32 smu = smem_u32(smem);
    const u32 bbase = smu + B_OFF;

    const int tid = threadIdx.x;
    const int warp = tid >> 5;
    const int lane = tid & 31;
    const int warpm = warp & 1;
    const int warpn = warp >> 1;   // 0..7, each 32 n

    const int TPH = H / R;
    const int b = blockIdx.x / TPH;
    const int h0 = (blockIdx.x % TPH) * R;
    const float* xb = x + (size_t)b * 128 * H * W;

    if (tid < 256) sCol[tid] = 0.f;

    // hoisted B-tile geometry (njp group 0 and 1)
    int p0[2];
#pragma unroll
    for (int j = 0; j < 2; j++) {
        int ng = warpn * 32 + j * 16 + (lane >> 4) * 8;
        int trow = ng >> LW;
        int tcol = ng & (W - 1);
        p0[j] = trow * NW + tcol + (lane & 7);
    }
    const int kbh = (lane >> 3) & 1;

    float d[4][4][4];
#pragma unroll
    for (int mi = 0; mi < 4; mi++)
#pragma unroll
        for (int nj = 0; nj < 4; nj++)
#pragma unroll
            for (int q = 0; q < 4; q++) d[mi][nj][q] = 0.f;

    for (int cc = 0; cc < 4; cc++) {
        __syncthreads();  // protect prior chunk's B readers
        // stage B: 32 channels x NP halo positions, fp16 pairs, swizzled.
        {
            const int c0ch = cc * 32;
            const int cp = tid >> 5;
            for (int p = tid & 31; p < NP; p += 32) {
                int r = p / NW;
                int w = p - r * NW;
                int hin = h0 + r - 1;
                int gw = w - 1;
                float v0 = 0.f, v1 = 0.f;
                if (hin >= 0 && hin < H && (unsigned)gw < (unsigned)W) {
                    const float* bp = xb + ((size_t)(c0ch + 2 * cp) * H + hin) * W + gw;
                    v0 = bp[0];
                    v1 = bp[H * W];
                }
                __half2 hv = __floats2half2_rn(v0, v1);
                int word = p * 20 + ((((cp >> 2) ^ (p & 3)) << 2)) + (cp & 3);
                *(__half2*)(smem + B_OFF + word * 4) = hv;
            }
        }
        __syncthreads();

        // 9 taps, straight-line (no barriers): A via LDG.128, B via ldmatrix
#pragma unroll
        for (int tap = 0; tap < 9; tap++) {
            const int gi = cc * 9 + tap;
            const int dy = tap / 3;
            const int dx = tap - dy * 3;
            const int pofs = dy * NW + dx;
#pragma unroll
            for (int ks = 0; ks < 2; ks++) {
                uint4 a[4];
#pragma unroll
                for (int mi = 0; mi < 4; mi++) {
                    int rg = warpm * 4 + mi;
                    a[mi] = wA[((gi * 8 + rg) * 2 + ks) * 32 + lane];
                }
                const int kb = ks * 2 + kbh;
#pragma unroll
                for (int j = 0; j < 2; j++) {
                    int p = p0[j] + pofs;
                    u32 bf[4];
                    ldm_x4(bf, bbase + p * 80 + ((kb ^ (p & 3)) << 4));
#pragma unroll
                    for (int mi = 0; mi < 4; mi++) {
                        mma16816(d[mi][2 * j], a[mi], bf[0], bf[1]);
                        mma16816(d[mi][2 * j + 1], a[mi], bf[2], bf[3]);
                    }
                }
            }
        }
    }

    // ---- epilogue: bias + ReLU + dot(w_t), reduce, pool -------------------
    const int g = lane >> 2;
    const int tid4 = lane & 3;
    float bsv[4][2], wtv[4][2];
#pragma unroll
    for (int mi = 0; mi < 4; mi++)
#pragma unroll
        for (int hh = 0; hh < 2; hh++) {
            int o = warpm * 64 + mi * 16 + hh * 8 + g;
            bsv[mi][hh] = bs[o];
            wtv[mi][hh] = wt[o];
        }
#pragma unroll
    for (int nj = 0; nj < 4; nj++) {
        float v0 = 0.f, v1 = 0.f;
#pragma unroll
        for (int mi = 0; mi < 4; mi++) {
            v0 += fmaxf(d[mi][nj][0] + bsv[mi][0], 0.f) * wtv[mi][0]
                + fmaxf(d[mi][nj][2] + bsv[mi][1], 0.f) * wtv[mi][1];
            v1 += fmaxf(d[mi][nj][1] + bsv[mi][0], 0.f) * wtv[mi][0]
                + fmaxf(d[mi][nj][3] + bsv[mi][1], 0.f) * wtv[mi][1];
        }
        v0 += __shfl_xor_sync(0xffffffffu, v0, 4);
        v0 += __shfl_xor_sync(0xffffffffu, v0, 8);
        v0 += __shfl_xor_sync(0xffffffffu, v0, 16);
        v1 += __shfl_xor_sync(0xffffffffu, v1, 4);
        v1 += __shfl_xor_sync(0xffffffffu, v1, 8);
        v1 += __shfl_xor_sync(0xffffffffu, v1, 16);
        if (lane < 4) {
            int n = warpn * 32 + nj * 8 + tid4 * 2;
            atomicAdd(&sCol[n], v0);
            atomicAdd(&sCol[n + 1], v1);
        }
    }
    __syncthreads();

    if (tid < W) {
        const float btv = bt[0];
        float s = 0.f;
#pragma unroll
        for (int r = 0; r < R; r++)
            s += wpl[h0 + r] * (sCol[r * W + tid] + btv);
        atomicAdd(&out[b * 240 + BASE + tid], s);
    }
}

// ---- p5 path: tidy 1x1 (512->1) + pool over h=8, memory bound -------------
__global__ void p5_kernel(const float* __restrict__ p5,
                          const float* __restrict__ wt,   // [512]
                          const float* __restrict__ bt,   // [1]
                          const float* __restrict__ wpl,  // [8]
                          const float* __restrict__ bpl,  // [1]
                          float* __restrict__ out) {
    const int b = blockIdx.x;
    const int tid = threadIdx.x;
    const int w = tid & 15;
    const int g = tid >> 4;
    __shared__ float red[256];
    __shared__ float spl[8];
    if (tid < 8) spl[tid] = wpl[tid];
    __syncthreads();

    const float* pb = p5 + (size_t)b * 512 * 8 * 16;
    float accv = 0.f;
    for (int c = g; c < 512; c += 16) {
        float wc = wt[c];
        const float* row = pb + (size_t)c * 8 * 16 + w;
#pragma unroll
        for (int h = 0; h < 8; h++)
            accv = fmaf(wc * spl[h], row[h * 16], accv);
    }
    red[tid] = accv;
    __syncthreads();
    if (tid < 16) {
        float s = 0.f;
#pragma unroll
        for (int gg = 0; gg < 16; gg++) s += red[gg * 16 + tid];
        float sumpl = 0.f;
#pragma unroll
        for (int h = 0; h < 8; h++) sumpl += spl[h];
        out[b * 240 + 224 + tid] = s + bt[0] * sumpl + bpl[0];
    }
}

// ---------------------------------------------------------------------------
extern "C" void kernel_launch(void* const* d_in, const int* in_sizes, int n_in,
                              void* d_out, int out_size) {
    const float* p2 = (const float*)d_in[0];
    const float* p3 = (const float*)d_in[1];
    const float* p4 = (const float*)d_in[2];
    const float* p5 = (const float*)d_in[3];
    const float* w_s1 = (const float*)d_in[4];
    const float* b_s1 = (const float*)d_in[5];
    const float* w_s2 = (const float*)d_in[6];
    const float* b_s2 = (const float*)d_in[7];
    const float* w_s3 = (const float*)d_in[8];
    const float* b_s3 = (const float*)d_in[9];
    const float* w_t1 = (const float*)d_in[10];
    const float* b_t1 = (const float*)d_in[11];
    const float* w_t2 = (const float*)d_in[12];
    const float* b_t2 = (const float*)d_in[13];
    const float* w_t3 = (const float*)d_in[14];
    const float* b_t3 = (const float*)d_in[15];
    const float* w_t4 = (const float*)d_in[16];
    const float* b_t4 = (const float*)d_in[17];
    const float* w_pl1 = (const float*)d_in[18];
    const float* b_pl1 = (const float*)d_in[19];
    const float* w_pl2 = (const float*)d_in[20];
    const float* b_pl2 = (const float*)d_in[21];
    const float* w_pl3 = (const float*)d_in[22];
    const float* b_pl3 = (const float*)d_in[23];
    const float* w_pl4 = (const float*)d_in[24];
    const float* b_pl4 = (const float*)d_in[25];
    float* out = (float*)d_out;

    prep_wA_kernel<<<(3 * 36 * 2048 + 255) / 256, 256>>>(w_s1, w_s2, w_s3);
    init_out_kernel<<<(64 * 224 + 255) / 256, 256>>>(b_pl1, b_pl2, b_pl3, out);

    uint4* wAd;
    cudaGetSymbolAddress((void**)&wAd, g_wA);

    // dynamic smem: 1024 + NP*80 bytes
    const int sm1 = 1024 + (2 + 2) * 130 * 80;  // 42624
    const int sm2 = 1024 + (4 + 2) * 66 * 80;   // 32704
    const int sm3 = 1024 + (8 + 2) * 34 * 80;   // 28224
    cudaFuncSetAttribute(conv_mma_kernel<64, 128, 7, 2, 0>,
                         cudaFuncAttributeMaxDynamicSharedMemorySize, sm1);
    cudaFuncSetAttribute(conv_mma_kernel<32, 64, 6, 4, 128>,
                         cudaFuncAttributeMaxDynamicSharedMemorySize, sm2);
    cudaFuncSetAttribute(conv_mma_kernel<16, 32, 5, 8, 192>,
                         cudaFuncAttributeMaxDynamicSharedMemorySize, sm3);

    conv_mma_kernel<64, 128, 7, 2, 0><<<64 * 32, 512, sm1>>>(
        p2, wAd + 0 * 36 * 512, b_s1, w_t1, b_t1, w_pl1, out);
    conv_mma_kernel<32, 64, 6, 4, 128><<<64 * 8, 512, sm2>>>(
        p3, wAd + 1 * 36 * 512, b_s2, w_t2, b_t2, w_pl2, out);
    conv_mma_kernel<16, 32, 5, 8, 192><<<64 * 2, 512, sm3>>>(
        p4, wAd + 2 * 36 * 512, b_s3, w_t3, b_t3, w_pl3, out);
    p5_kernel<<<64, 256>>>(p5, w_t4, b_t4, w_pl4, b_pl4, out);
}